// round 2
// baseline (speedup 1.0000x reference)
#include <cuda_runtime.h>
#include <cuda_bf16.h>
#include <math.h>

// Problem constants (fixed by the reference)
#define BATCH     65536
#define EMBED_DIM 128
#define NEG_K     5

#define WARPS_PER_BLOCK 32
#define BLOCK_THREADS   (WARPS_PER_BLOCK * 32)            // 1024
#define NUM_BLOCKS      (BATCH / WARPS_PER_BLOCK)         // 2048

// Scratch (allocation-free per harness rules)
__device__ float        g_partials[NUM_BLOCKS];
__device__ unsigned int g_done_count = 0;

__device__ __forceinline__ float log_sigmoid(float x) {
    // stable: min(x,0) - log1p(exp(-|x|))
    return fminf(x, 0.0f) - log1pf(__expf(-fabsf(x)));
}

__global__ __launch_bounds__(BLOCK_THREADS)
void skipgram_loss_kernel(const int* __restrict__ center,
                          const int* __restrict__ context,
                          const int* __restrict__ negatives,
                          const float* __restrict__ u_weight,
                          const float* __restrict__ v_weight,
                          float* __restrict__ out) {
    const int warp_in_block = threadIdx.x >> 5;
    const int lane          = threadIdx.x & 31;
    const int b             = blockIdx.x * WARPS_PER_BLOCK + warp_in_block;

    // ---- gather indices (broadcast loads) ----
    const int ci = center[b];
    const int xi = context[b];
    int ni[NEG_K];
#pragma unroll
    for (int k = 0; k < NEG_K; k++) ni[k] = negatives[b * NEG_K + k];

    // ---- issue all 7 row loads up front (MLP=7 per lane) ----
    const float4* cp = reinterpret_cast<const float4*>(u_weight + (size_t)ci * EMBED_DIM);
    const float4* xp = reinterpret_cast<const float4*>(v_weight + (size_t)xi * EMBED_DIM);
    float4 c4 = __ldg(cp + lane);
    float4 x4 = __ldg(xp + lane);
    float4 n4[NEG_K];
#pragma unroll
    for (int k = 0; k < NEG_K; k++) {
        const float4* np = reinterpret_cast<const float4*>(v_weight + (size_t)ni[k] * EMBED_DIM);
        n4[k] = __ldg(np + lane);
    }

    // ---- 6 partial dot products per lane ----
    float acc[1 + NEG_K];
    acc[0] = c4.x * x4.x + c4.y * x4.y + c4.z * x4.z + c4.w * x4.w;
#pragma unroll
    for (int k = 0; k < NEG_K; k++) {
        acc[1 + k] = c4.x * n4[k].x + c4.y * n4[k].y + c4.z * n4[k].z + c4.w * n4[k].w;
    }

    // ---- butterfly warp reduction of all 6 dots ----
#pragma unroll
    for (int off = 16; off > 0; off >>= 1) {
#pragma unroll
        for (int j = 0; j < 1 + NEG_K; j++) {
            acc[j] += __shfl_xor_sync(0xFFFFFFFFu, acc[j], off);
        }
    }

    // ---- per-element loss, one value per warp ----
    __shared__ float smem[WARPS_PER_BLOCK];
    if (lane == 0) {
        float pos_loss = log_sigmoid(acc[0]);
        float neg_loss = 0.0f;
#pragma unroll
        for (int k = 0; k < NEG_K; k++) {
            neg_loss += log_sigmoid(-acc[1 + k]);
        }
        smem[warp_in_block] = -(pos_loss + neg_loss);
    }
    __syncthreads();

    // ---- block reduction: warp 0 reduces the 32 warp sums ----
    if (warp_in_block == 0) {
        float s = smem[lane];
#pragma unroll
        for (int off = 16; off > 0; off >>= 1) {
            s += __shfl_xor_sync(0xFFFFFFFFu, s, off);
        }
        if (lane == 0) g_partials[blockIdx.x] = s;
    }

    // ---- last-block-done final reduction (no second kernel) ----
    __shared__ bool is_last;
    __threadfence();
    __syncthreads();
    if (threadIdx.x == 0) {
        unsigned int prev = atomicAdd(&g_done_count, 1u);
        is_last = (prev == (unsigned int)(NUM_BLOCKS - 1));
    }
    __syncthreads();

    if (is_last) {
        // NUM_BLOCKS = 2048 partials, BLOCK_THREADS = 1024 -> 2 per thread
        double s = (double)g_partials[threadIdx.x]
                 + (double)g_partials[threadIdx.x + BLOCK_THREADS];
        // warp reduce (double)
#pragma unroll
        for (int off = 16; off > 0; off >>= 1) {
            s += __shfl_xor_sync(0xFFFFFFFFu, s, off);
        }
        __shared__ double dsm[WARPS_PER_BLOCK];
        if (lane == 0) dsm[warp_in_block] = s;
        __syncthreads();
        if (warp_in_block == 0) {
            double t = dsm[lane];
#pragma unroll
            for (int off = 16; off > 0; off >>= 1) {
                t += __shfl_xor_sync(0xFFFFFFFFu, t, off);
            }
            if (lane == 0) {
                out[0] = (float)(t * (1.0 / (double)BATCH));
                g_done_count = 0;   // reset for next graph replay
            }
        }
    }
}

extern "C" void kernel_launch(void* const* d_in, const int* in_sizes, int n_in,
                              void* d_out, int out_size) {
    // metadata order: center_nodes, context_nodes, negative_nodes, u_weight, v_weight
    const int*   center    = (const int*)d_in[0];
    const int*   context   = (const int*)d_in[1];
    const int*   negatives = (const int*)d_in[2];
    const float* u_weight  = (const float*)d_in[3];
    const float* v_weight  = (const float*)d_in[4];
    float*       out       = (float*)d_out;

    skipgram_loss_kernel<<<NUM_BLOCKS, BLOCK_THREADS>>>(center, context, negatives,
                                                        u_weight, v_weight, out);
}

// round 3
// speedup vs baseline: 1.4520x; 1.4520x over previous
#include <cuda_runtime.h>
#include <cuda_bf16.h>
#include <math.h>

// Problem constants (fixed by the reference)
#define BATCH     65536
#define EMBED_DIM 128
#define NEG_K     5

#define WARPS_PER_BLOCK 8
#define BLOCK_THREADS   (WARPS_PER_BLOCK * 32)            // 256
#define NUM_BLOCKS      (BATCH / WARPS_PER_BLOCK)         // 8192

#define SCALE      4294967296.0   // 2^32
#define INV_SCALE  (1.0 / 4294967296.0)

// Scratch (allocation-free per harness rules).
// Integer accumulator => order-independent => deterministic output.
__device__ long long    g_isum = 0;
__device__ unsigned int g_done_count = 0;

__device__ __forceinline__ float log_sigmoid(float x) {
    // stable: min(x,0) - log1p(exp(-|x|))
    return fminf(x, 0.0f) - log1pf(__expf(-fabsf(x)));
}

__global__ __launch_bounds__(BLOCK_THREADS)
void skipgram_loss_kernel(const int* __restrict__ center,
                          const int* __restrict__ context,
                          const int* __restrict__ negatives,
                          const float* __restrict__ u_weight,
                          const float* __restrict__ v_weight,
                          float* __restrict__ out) {
    const int warp_in_block = threadIdx.x >> 5;
    const int lane          = threadIdx.x & 31;
    const int b             = blockIdx.x * WARPS_PER_BLOCK + warp_in_block;

    // ---- gather indices (broadcast loads) ----
    const int ci = center[b];
    const int xi = context[b];
    int ni[NEG_K];
#pragma unroll
    for (int k = 0; k < NEG_K; k++) ni[k] = negatives[b * NEG_K + k];

    // ---- issue all 7 row loads up front (MLP=7 per lane) ----
    const float4* cp = reinterpret_cast<const float4*>(u_weight + (size_t)ci * EMBED_DIM);
    const float4* xp = reinterpret_cast<const float4*>(v_weight + (size_t)xi * EMBED_DIM);
    float4 c4 = __ldg(cp + lane);
    float4 x4 = __ldg(xp + lane);
    float4 n4[NEG_K];
#pragma unroll
    for (int k = 0; k < NEG_K; k++) {
        const float4* np = reinterpret_cast<const float4*>(v_weight + (size_t)ni[k] * EMBED_DIM);
        n4[k] = __ldg(np + lane);
    }

    // ---- 6 partial dot products per lane ----
    float acc[1 + NEG_K];
    acc[0] = c4.x * x4.x + c4.y * x4.y + c4.z * x4.z + c4.w * x4.w;
#pragma unroll
    for (int k = 0; k < NEG_K; k++) {
        acc[1 + k] = c4.x * n4[k].x + c4.y * n4[k].y + c4.z * n4[k].z + c4.w * n4[k].w;
    }

    // ---- butterfly warp reduction of all 6 dots ----
#pragma unroll
    for (int off = 16; off > 0; off >>= 1) {
#pragma unroll
        for (int j = 0; j < 1 + NEG_K; j++) {
            acc[j] += __shfl_xor_sync(0xFFFFFFFFu, acc[j], off);
        }
    }

    // ---- per-element loss, one value per warp ----
    __shared__ float smem[WARPS_PER_BLOCK];
    if (lane == 0) {
        float pos_loss = log_sigmoid(acc[0]);
        float neg_loss = 0.0f;
#pragma unroll
        for (int k = 0; k < NEG_K; k++) {
            neg_loss += log_sigmoid(-acc[1 + k]);
        }
        smem[warp_in_block] = -(pos_loss + neg_loss);
    }
    __syncthreads();

    // ---- block reduction (warp 0, 8 values) + deterministic integer atomic ----
    if (threadIdx.x == 0) {
        double s = 0.0;
#pragma unroll
        for (int w = 0; w < WARPS_PER_BLOCK; w++) s += (double)smem[w];
        long long q = __double2ll_rn(s * SCALE);
        atomicAdd((unsigned long long*)&g_isum, (unsigned long long)q);
        __threadfence();
        unsigned int prev = atomicAdd(&g_done_count, 1u);
        if (prev == (unsigned int)(NUM_BLOCKS - 1)) {
            // last block: all integer adds are visible (L2 atomics + fence ordering)
            long long total = (long long)atomicAdd((unsigned long long*)&g_isum, 0ULL);
            out[0] = (float)((double)total * INV_SCALE / (double)BATCH);
            // reset for next graph replay
            g_isum = 0;
            g_done_count = 0;
        }
    }
}

extern "C" void kernel_launch(void* const* d_in, const int* in_sizes, int n_in,
                              void* d_out, int out_size) {
    // metadata order: center_nodes, context_nodes, negative_nodes, u_weight, v_weight
    const int*   center    = (const int*)d_in[0];
    const int*   context   = (const int*)d_in[1];
    const int*   negatives = (const int*)d_in[2];
    const float* u_weight  = (const float*)d_in[3];
    const float* v_weight  = (const float*)d_in[4];
    float*       out       = (float*)d_out;

    skipgram_loss_kernel<<<NUM_BLOCKS, BLOCK_THREADS>>>(center, context, negatives,
                                                        u_weight, v_weight, out);
}

// round 5
// speedup vs baseline: 1.5074x; 1.0381x over previous
#include <cuda_runtime.h>
#include <cuda_bf16.h>
#include <math.h>

// Problem constants (fixed by the reference)
#define BATCH     65536
#define EMBED_DIM 128
#define NEG_K     5

#define WARPS_PER_BLOCK 8
#define BLOCK_THREADS   (WARPS_PER_BLOCK * 32)            // 256
#define NUM_BLOCKS      (BATCH / WARPS_PER_BLOCK)         // 8192

// Fixed-point packing: low 48 bits = sum of round(block_sum * 2^24),
// bits [48:63] = block arrival count (16 bits: 8192 arrivals, no overflow —
// R4 failed because the count field at bit 52 wrapped at 4096).
// Per-element loss is >= 0 (loss = -(sum of log_sigmoid), log_sigmoid <= 0)
// and ~4.16, so total*2^24 ~ 4.6e12 << 2^48. Integer adds are associative ->
// deterministic regardless of arrival order; the block whose returned old
// value carries count NUM_BLOCKS-1 holds the complete total after adding its
// own contribution. No fences, no second atomic, no extra reads.
#define Q_SCALE     16777216.0            // 2^24
#define INV_Q_SCALE (1.0 / 16777216.0)
#define COUNT_SHIFT 48
#define COUNT_ONE   (1ULL << COUNT_SHIFT)
#define SUM_MASK    ((1ULL << COUNT_SHIFT) - 1ULL)

__device__ unsigned long long g_packed = 0ULL;

__device__ __forceinline__ float log_sigmoid(float x) {
    // stable: min(x,0) - log1p(exp(-|x|))
    return fminf(x, 0.0f) - log1pf(__expf(-fabsf(x)));
}

__global__ __launch_bounds__(BLOCK_THREADS)
void skipgram_loss_kernel(const int* __restrict__ center,
                          const int* __restrict__ context,
                          const int* __restrict__ negatives,
                          const float* __restrict__ u_weight,
                          const float* __restrict__ v_weight,
                          float* __restrict__ out) {
    const int warp_in_block = threadIdx.x >> 5;
    const int lane          = threadIdx.x & 31;
    const int b             = blockIdx.x * WARPS_PER_BLOCK + warp_in_block;

    // ---- gather indices (broadcast loads) ----
    const int ci = center[b];
    const int xi = context[b];
    int ni[NEG_K];
#pragma unroll
    for (int k = 0; k < NEG_K; k++) ni[k] = negatives[b * NEG_K + k];

    // ---- issue all 7 row loads up front (MLP=7 per lane) ----
    const float4* cp = reinterpret_cast<const float4*>(u_weight + (size_t)ci * EMBED_DIM);
    const float4* xp = reinterpret_cast<const float4*>(v_weight + (size_t)xi * EMBED_DIM);
    float4 c4 = __ldg(cp + lane);
    float4 x4 = __ldg(xp + lane);
    float4 n4[NEG_K];
#pragma unroll
    for (int k = 0; k < NEG_K; k++) {
        const float4* np = reinterpret_cast<const float4*>(v_weight + (size_t)ni[k] * EMBED_DIM);
        n4[k] = __ldg(np + lane);
    }

    // ---- 6 partial dot products per lane ----
    float acc[1 + NEG_K];
    acc[0] = c4.x * x4.x + c4.y * x4.y + c4.z * x4.z + c4.w * x4.w;
#pragma unroll
    for (int k = 0; k < NEG_K; k++) {
        acc[1 + k] = c4.x * n4[k].x + c4.y * n4[k].y + c4.z * n4[k].z + c4.w * n4[k].w;
    }

    // ---- butterfly warp reduction of all 6 dots ----
#pragma unroll
    for (int off = 16; off > 0; off >>= 1) {
#pragma unroll
        for (int j = 0; j < 1 + NEG_K; j++) {
            acc[j] += __shfl_xor_sync(0xFFFFFFFFu, acc[j], off);
        }
    }

    // ---- per-element loss, one value per warp ----
    __shared__ float smem[WARPS_PER_BLOCK];
    if (lane == 0) {
        float pos_loss = log_sigmoid(acc[0]);
        float neg_loss = 0.0f;
#pragma unroll
        for (int k = 0; k < NEG_K; k++) {
            neg_loss += log_sigmoid(-acc[1 + k]);
        }
        smem[warp_in_block] = -(pos_loss + neg_loss);
    }
    __syncthreads();

    // ---- block reduction + single packed atomic (fence-free, deterministic) ----
    if (threadIdx.x == 0) {
        double s = 0.0;
#pragma unroll
        for (int w = 0; w < WARPS_PER_BLOCK; w++) s += (double)smem[w];
        // loss >= 0 by construction; quantize to fixed point
        unsigned long long q = (unsigned long long)__double2ll_rn(s * Q_SCALE);
        unsigned long long my_add = COUNT_ONE + q;
        unsigned long long old = atomicAdd(&g_packed, my_add);
        if ((old >> COUNT_SHIFT) == (unsigned long long)(NUM_BLOCKS - 1)) {
            // I'm the last arrival: old + my_add is the complete packed total.
            unsigned long long total = old + my_add;
            double sum = (double)(long long)(total & SUM_MASK) * INV_Q_SCALE;
            out[0] = (float)(sum / (double)BATCH);
            g_packed = 0ULL;   // reset for next graph replay (kernel-boundary ordered)
        }
    }
}

extern "C" void kernel_launch(void* const* d_in, const int* in_sizes, int n_in,
                              void* d_out, int out_size) {
    // metadata order: center_nodes, context_nodes, negative_nodes, u_weight, v_weight
    const int*   center    = (const int*)d_in[0];
    const int*   context   = (const int*)d_in[1];
    const int*   negatives = (const int*)d_in[2];
    const float* u_weight  = (const float*)d_in[3];
    const float* v_weight  = (const float*)d_in[4];
    float*       out       = (float*)d_out;

    skipgram_loss_kernel<<<NUM_BLOCKS, BLOCK_THREADS>>>(center, context, negatives,
                                                        u_weight, v_weight, out);
}

// round 6
// speedup vs baseline: 1.8200x; 1.2074x over previous
#include <cuda_runtime.h>
#include <cuda_bf16.h>
#include <math.h>

// Problem constants (fixed by the reference)
#define BATCH     65536
#define EMBED_DIM 128
#define NEG_K     5

#define WARPS_PER_BLOCK 8
#define BLOCK_THREADS   (WARPS_PER_BLOCK * 32)            // 256
#define NUM_BLOCKS      (BATCH / WARPS_PER_BLOCK)         // 8192

// Fixed-point packing: low 48 bits = sum of round(block_sum * 2^24),
// bits [48:63] = block arrival count (16 bits: 8192 arrivals, no overflow).
// Per-element loss is >= 0 (loss = -(sum of log_sigmoid), log_sigmoid <= 0)
// and ~4.16, so total*2^24 ~ 4.6e12 << 2^48. Integer adds are associative ->
// deterministic regardless of arrival order; the block whose returned old
// value carries count NUM_BLOCKS-1 holds the complete total after adding its
// own contribution. No fences, no second atomic, no extra reads.
#define Q_SCALE     16777216.0            // 2^24
#define INV_Q_SCALE (1.0 / 16777216.0)
#define COUNT_SHIFT 48
#define COUNT_ONE   (1ULL << COUNT_SHIFT)
#define SUM_MASK    ((1ULL << COUNT_SHIFT) - 1ULL)

__device__ unsigned long long g_packed = 0ULL;

__device__ __forceinline__ float log_sigmoid(float x) {
    // stable: min(x,0) - log1p(exp(-|x|))
    return fminf(x, 0.0f) - log1pf(__expf(-fabsf(x)));
}

__global__ __launch_bounds__(BLOCK_THREADS, 8)   // force regs <= 32 -> 8 blocks/SM (64 warps)
void skipgram_loss_kernel(const int* __restrict__ center,
                          const int* __restrict__ context,
                          const int* __restrict__ negatives,
                          const float* __restrict__ u_weight,
                          const float* __restrict__ v_weight,
                          float* __restrict__ out) {
    const int warp_in_block = threadIdx.x >> 5;
    const int lane          = threadIdx.x & 31;
    const int b             = blockIdx.x * WARPS_PER_BLOCK + warp_in_block;

    // ---- gather indices (broadcast loads) ----
    const int ci = center[b];
    const int xi = context[b];
    int ni[NEG_K];
#pragma unroll
    for (int k = 0; k < NEG_K; k++) ni[k] = negatives[b * NEG_K + k];

    // ---- issue all 7 row loads up front (MLP=7 per lane) ----
    const float4* cp = reinterpret_cast<const float4*>(u_weight + (size_t)ci * EMBED_DIM);
    const float4* xp = reinterpret_cast<const float4*>(v_weight + (size_t)xi * EMBED_DIM);
    float4 c4 = __ldg(cp + lane);
    float4 x4 = __ldg(xp + lane);
    float4 n4[NEG_K];
#pragma unroll
    for (int k = 0; k < NEG_K; k++) {
        const float4* np = reinterpret_cast<const float4*>(v_weight + (size_t)ni[k] * EMBED_DIM);
        n4[k] = __ldg(np + lane);
    }

    // ---- 6 partial dot products per lane ----
    float acc[1 + NEG_K];
    acc[0] = c4.x * x4.x + c4.y * x4.y + c4.z * x4.z + c4.w * x4.w;
#pragma unroll
    for (int k = 0; k < NEG_K; k++) {
        acc[1 + k] = c4.x * n4[k].x + c4.y * n4[k].y + c4.z * n4[k].z + c4.w * n4[k].w;
    }

    // ---- butterfly warp reduction of all 6 dots ----
#pragma unroll
    for (int off = 16; off > 0; off >>= 1) {
#pragma unroll
        for (int j = 0; j < 1 + NEG_K; j++) {
            acc[j] += __shfl_xor_sync(0xFFFFFFFFu, acc[j], off);
        }
    }

    // ---- per-element loss, one value per warp ----
    __shared__ float smem[WARPS_PER_BLOCK];
    if (lane == 0) {
        float pos_loss = log_sigmoid(acc[0]);
        float neg_loss = 0.0f;
#pragma unroll
        for (int k = 0; k < NEG_K; k++) {
            neg_loss += log_sigmoid(-acc[1 + k]);
        }
        smem[warp_in_block] = -(pos_loss + neg_loss);
    }
    __syncthreads();

    // ---- block reduction (fixed-order float: deterministic, cheap) ----
    if (threadIdx.x == 0) {
        float s = 0.0f;
#pragma unroll
        for (int w = 0; w < WARPS_PER_BLOCK; w++) s += smem[w];
        // loss >= 0 by construction; quantize to fixed point
        unsigned long long q = (unsigned long long)__double2ll_rn((double)s * Q_SCALE);
        unsigned long long my_add = COUNT_ONE + q;
        unsigned long long old = atomicAdd(&g_packed, my_add);
        if ((old >> COUNT_SHIFT) == (unsigned long long)(NUM_BLOCKS - 1)) {
            // I'm the last arrival: old + my_add is the complete packed total.
            unsigned long long total = old + my_add;
            double sum = (double)(long long)(total & SUM_MASK) * INV_Q_SCALE;
            out[0] = (float)(sum / (double)BATCH);
            g_packed = 0ULL;   // reset for next graph replay (kernel-boundary ordered)
        }
    }
}

extern "C" void kernel_launch(void* const* d_in, const int* in_sizes, int n_in,
                              void* d_out, int out_size) {
    // metadata order: center_nodes, context_nodes, negative_nodes, u_weight, v_weight
    const int*   center    = (const int*)d_in[0];
    const int*   context   = (const int*)d_in[1];
    const int*   negatives = (const int*)d_in[2];
    const float* u_weight  = (const float*)d_in[3];
    const float* v_weight  = (const float*)d_in[4];
    float*       out       = (float*)d_out;

    skipgram_loss_kernel<<<NUM_BLOCKS, BLOCK_THREADS>>>(center, context, negatives,
                                                        u_weight, v_weight, out);
}

// round 7
// speedup vs baseline: 1.9307x; 1.0608x over previous
#include <cuda_runtime.h>
#include <cuda_bf16.h>
#include <math.h>

// Problem constants (fixed by the reference)
#define BATCH     65536
#define EMBED_DIM 128
#define NEG_K     5

#define WARPS_PER_BLOCK 4
#define BLOCK_THREADS   (WARPS_PER_BLOCK * 32)                 // 128
#define ELEMS_PER_WARP  2
#define NUM_BLOCKS      (BATCH / (WARPS_PER_BLOCK * ELEMS_PER_WARP))  // 8192

// Fixed-point packed accumulator+counter (see R5): low 48 bits = sum of
// round(block_sum * 2^24) [loss >= 0, total*2^24 ~ 4.6e12 << 2^48],
// bits [48:63] = arrival count (8192 max, 16-bit field). Integer adds are
// associative -> deterministic; last arrival holds the complete total.
#define Q_SCALE     16777216.0            // 2^24
#define INV_Q_SCALE (1.0 / 16777216.0)
#define COUNT_SHIFT 48
#define COUNT_ONE   (1ULL << COUNT_SHIFT)
#define SUM_MASK    ((1ULL << COUNT_SHIFT) - 1ULL)

__device__ unsigned long long g_packed = 0ULL;

__device__ __forceinline__ float log_sigmoid(float x) {
    // stable: min(x,0) - log1p(exp(-|x|))
    return fminf(x, 0.0f) - log1pf(__expf(-fabsf(x)));
}

__device__ __forceinline__ float dot4(float4 a, float4 b) {
    return a.x * b.x + a.y * b.y + a.z * b.z + a.w * b.w;
}

__global__ __launch_bounds__(BLOCK_THREADS, 5)   // cap ~102 regs: room for 14 live float4, no spills
void skipgram_loss_kernel(const int* __restrict__ center,
                          const int* __restrict__ context,
                          const int* __restrict__ negatives,
                          const float* __restrict__ u_weight,
                          const float* __restrict__ v_weight,
                          float* __restrict__ out) {
    const int warp_in_block = threadIdx.x >> 5;
    const int lane          = threadIdx.x & 31;
    const int wg            = blockIdx.x * WARPS_PER_BLOCK + warp_in_block;
    const int b0            = wg * ELEMS_PER_WARP;   // even -> negatives base is 8B-aligned

    // ---- gather indices for both elements (vectorized negatives: 5x int2) ----
    const int ci0 = center[b0],  ci1 = center[b0 + 1];
    const int xi0 = context[b0], xi1 = context[b0 + 1];
    const int2* nv = reinterpret_cast<const int2*>(negatives + (size_t)b0 * NEG_K);
    int2 q0 = __ldg(nv + 0), q1 = __ldg(nv + 1), q2 = __ldg(nv + 2),
         q3 = __ldg(nv + 3), q4 = __ldg(nv + 4);
    const int n0[NEG_K] = { q0.x, q0.y, q1.x, q1.y, q2.x };
    const int n1[NEG_K] = { q2.y, q3.x, q3.y, q4.x, q4.y };

    // ---- issue all 14 row loads back-to-back (MLP=14 per lane) ----
    const float4* c0p = reinterpret_cast<const float4*>(u_weight + (size_t)ci0 * EMBED_DIM);
    const float4* c1p = reinterpret_cast<const float4*>(u_weight + (size_t)ci1 * EMBED_DIM);
    const float4* x0p = reinterpret_cast<const float4*>(v_weight + (size_t)xi0 * EMBED_DIM);
    const float4* x1p = reinterpret_cast<const float4*>(v_weight + (size_t)xi1 * EMBED_DIM);
    float4 c40 = __ldg(c0p + lane);
    float4 c41 = __ldg(c1p + lane);
    float4 x40 = __ldg(x0p + lane);
    float4 x41 = __ldg(x1p + lane);
    float4 n40[NEG_K], n41[NEG_K];
#pragma unroll
    for (int k = 0; k < NEG_K; k++) {
        n40[k] = __ldg(reinterpret_cast<const float4*>(v_weight + (size_t)n0[k] * EMBED_DIM) + lane);
    }
#pragma unroll
    for (int k = 0; k < NEG_K; k++) {
        n41[k] = __ldg(reinterpret_cast<const float4*>(v_weight + (size_t)n1[k] * EMBED_DIM) + lane);
    }

    // ---- 12 partial dot products per lane ----
    float acc0[1 + NEG_K], acc1[1 + NEG_K];
    acc0[0] = dot4(c40, x40);
    acc1[0] = dot4(c41, x41);
#pragma unroll
    for (int k = 0; k < NEG_K; k++) {
        acc0[1 + k] = dot4(c40, n40[k]);
        acc1[1 + k] = dot4(c41, n41[k]);
    }

    // ---- butterfly warp reduction of all 12 dots (ILP across accumulators) ----
#pragma unroll
    for (int off = 16; off > 0; off >>= 1) {
#pragma unroll
        for (int j = 0; j < 1 + NEG_K; j++) {
            acc0[j] += __shfl_xor_sync(0xFFFFFFFFu, acc0[j], off);
            acc1[j] += __shfl_xor_sync(0xFFFFFFFFu, acc1[j], off);
        }
    }

    // ---- per-element losses: lane 0 handles elem0, lane 1 handles elem1 ----
    float l = 0.0f;
    if (lane == 0) {
        float neg_loss = 0.0f;
#pragma unroll
        for (int k = 0; k < NEG_K; k++) neg_loss += log_sigmoid(-acc0[1 + k]);
        l = -(log_sigmoid(acc0[0]) + neg_loss);
    } else if (lane == 1) {
        float neg_loss = 0.0f;
#pragma unroll
        for (int k = 0; k < NEG_K; k++) neg_loss += log_sigmoid(-acc1[1 + k]);
        l = -(log_sigmoid(acc1[0]) + neg_loss);
    }
    l += __shfl_xor_sync(0xFFFFFFFFu, l, 1);   // lane 0 now has loss0 + loss1

    __shared__ float smem[WARPS_PER_BLOCK];
    if (lane == 0) smem[warp_in_block] = l;
    __syncthreads();

    // ---- block reduction (fixed-order float) + single packed atomic ----
    if (threadIdx.x == 0) {
        float s = 0.0f;
#pragma unroll
        for (int w = 0; w < WARPS_PER_BLOCK; w++) s += smem[w];
        unsigned long long q = (unsigned long long)__double2ll_rn((double)s * Q_SCALE);
        unsigned long long my_add = COUNT_ONE + q;
        unsigned long long old = atomicAdd(&g_packed, my_add);
        if ((old >> COUNT_SHIFT) == (unsigned long long)(NUM_BLOCKS - 1)) {
            unsigned long long total = old + my_add;
            double sum = (double)(long long)(total & SUM_MASK) * INV_Q_SCALE;
            out[0] = (float)(sum / (double)BATCH);
            g_packed = 0ULL;   // reset for next graph replay (kernel-boundary ordered)
        }
    }
}

extern "C" void kernel_launch(void* const* d_in, const int* in_sizes, int n_in,
                              void* d_out, int out_size) {
    // metadata order: center_nodes, context_nodes, negative_nodes, u_weight, v_weight
    const int*   center    = (const int*)d_in[0];
    const int*   context   = (const int*)d_in[1];
    const int*   negatives = (const int*)d_in[2];
    const float* u_weight  = (const float*)d_in[3];
    const float* v_weight  = (const float*)d_in[4];
    float*       out       = (float*)d_out;

    skipgram_loss_kernel<<<NUM_BLOCKS, BLOCK_THREADS>>>(center, context, negatives,
                                                        u_weight, v_weight, out);
}